// round 1
// baseline (speedup 1.0000x reference)
#include <cuda_runtime.h>
#include <cstdint>

#define N_    32
#define CIN   256
#define COUT  512
#define H_    56
#define W_    56
#define HW    3136            // 56*56
#define EPSV  1e-5f
#define DW_TH 4.0f
#define PW_TH 1e-3f

// Scratch (no allocs allowed): intermediate y (post DW+BN+ReLU+cut) and per-(n,o) max bits.
__device__ __align__(16) float g_y[(size_t)N_ * CIN * HW];   // ~103 MB
__device__ int g_zmax[N_ * COUT];

// ---------------------------------------------------------------------------
// K0: zero the per-plane max accumulator
// ---------------------------------------------------------------------------
__global__ void k_zero_max() {
    int i = blockIdx.x * blockDim.x + threadIdx.x;
    if (i < N_ * COUT) g_zmax[i] = 0;
}

// ---------------------------------------------------------------------------
// K1: depthwise 3x3 conv + bias + BN1 + ReLU + per-plane cut (th=4.0)
// One block per (n, c) plane. Whole plane in smem -> cut applied in-kernel.
// ---------------------------------------------------------------------------
__global__ __launch_bounds__(256)
void k_dw(const float* __restrict__ x,
          const float* __restrict__ dww,  const float* __restrict__ dwb,
          const float* __restrict__ g1,   const float* __restrict__ b1,
          const float* __restrict__ m1,   const float* __restrict__ v1)
{
    __shared__ float sx[58 * 58];
    __shared__ float sy[HW];
    __shared__ float smax[256];

    const int bid = blockIdx.x;            // n*CIN + c
    const int c   = bid & (CIN - 1);
    const int tid = threadIdx.x;
    const float* __restrict__ xp = x + (size_t)bid * HW;

    // load 58x58 halo with zero padding
    for (int i = tid; i < 58 * 58; i += 256) {
        int r = i / 58, q = i - r * 58;
        int gh = r - 1, gw = q - 1;
        float v = 0.f;
        if ((unsigned)gh < 56u && (unsigned)gw < 56u) v = xp[gh * 56 + gw];
        sx[i] = v;
    }

    // per-channel constants
    const float w0 = __ldg(&dww[c * 9 + 0]);
    const float w1 = __ldg(&dww[c * 9 + 1]);
    const float w2 = __ldg(&dww[c * 9 + 2]);
    const float w3 = __ldg(&dww[c * 9 + 3]);
    const float w4 = __ldg(&dww[c * 9 + 4]);
    const float w5 = __ldg(&dww[c * 9 + 5]);
    const float w6 = __ldg(&dww[c * 9 + 6]);
    const float w7 = __ldg(&dww[c * 9 + 7]);
    const float w8 = __ldg(&dww[c * 9 + 8]);
    const float a  = __ldg(&g1[c]) * rsqrtf(__ldg(&v1[c]) + EPSV);
    const float sh = __ldg(&b1[c]) - __ldg(&m1[c]) * a + __ldg(&dwb[c]) * a;

    __syncthreads();

    float lmax = 0.f;
    for (int i = tid; i < HW; i += 256) {
        int h = i / 56, w = i - h * 56;
        const float* p = &sx[h * 58 + w];
        float acc = p[0]   * w0 + p[1]   * w1 + p[2]   * w2
                  + p[58]  * w3 + p[59]  * w4 + p[60]  * w5
                  + p[116] * w6 + p[117] * w7 + p[118] * w8;
        float val = fmaxf(fmaf(acc, a, sh), 0.f);
        sy[i] = val;
        lmax = fmaxf(lmax, val);
    }
    smax[tid] = lmax;
    __syncthreads();
    #pragma unroll
    for (int s = 128; s > 0; s >>= 1) {
        if (tid < s) smax[tid] = fmaxf(smax[tid], smax[tid + s]);
        __syncthreads();
    }
    const bool cut = smax[0] < DW_TH;

    float* __restrict__ yp = g_y + (size_t)bid * HW;
    for (int i = tid; i < HW; i += 256) yp[i] = cut ? 0.f : sy[i];
}

// ---------------------------------------------------------------------------
// K2: pointwise GEMM  Z[o,hw] = W[o,:] . Y[:,hw]  (per n)
// tile: 128(o) x 64(hw) x 8(k), 256 threads, 8x4 register tile
// fused bias + BN2 + ReLU, per-(n,o) plane max via smem + global atomicMax
// ---------------------------------------------------------------------------
__global__ __launch_bounds__(256)
void k_pw(const float* __restrict__ pw,  const float* __restrict__ pb,
          const float* __restrict__ g2,  const float* __restrict__ b2a,
          const float* __restrict__ m2,  const float* __restrict__ v2,
          float* __restrict__ out)
{
    __shared__ float Ws[8][128];
    __shared__ float Ys[8][64];
    __shared__ int   smaxb[128];

    const int tid = threadIdx.x;
    const int tx  = tid & 15;        // hw lane  (hw = hw0 + tx + j*16)
    const int ty  = tid >> 4;        // o  lane  (o  = o0  + ty + i*16)

    const int hw0 = blockIdx.x * 64;      // 49 tiles
    const int o0  = blockIdx.y * 128;     // 4 tiles
    const int n   = blockIdx.z;           // 32

    const float* __restrict__ Yg = g_y + (size_t)n * CIN * HW;

    // load mappings
    const int wi = tid >> 1;              // 0..127 (o row)
    const int wk = (tid & 1) * 4;         // 0 or 4
    const int yk = tid >> 5;              // 0..7 (k row)
    const int yj = (tid & 31) * 2;        // 0..62

    float acc[8][4];
    #pragma unroll
    for (int i = 0; i < 8; ++i)
        #pragma unroll
        for (int j = 0; j < 4; ++j) acc[i][j] = 0.f;

    if (tid < 128) smaxb[tid] = 0;

    for (int kt = 0; kt < CIN / 8; ++kt) {
        const int k0 = kt * 8;
        // stage loads into registers
        float4 wv = *(const float4*)&pw[(size_t)(o0 + wi) * CIN + k0 + wk];
        float2 yv = *(const float2*)&Yg[(size_t)(k0 + yk) * HW + hw0 + yj];
        __syncthreads();          // previous compute done before overwrite
        Ws[wk + 0][wi] = wv.x;
        Ws[wk + 1][wi] = wv.y;
        Ws[wk + 2][wi] = wv.z;
        Ws[wk + 3][wi] = wv.w;
        Ys[yk][yj]     = yv.x;
        Ys[yk][yj + 1] = yv.y;
        __syncthreads();

        #pragma unroll
        for (int k = 0; k < 8; ++k) {
            float wr[8], yr[4];
            #pragma unroll
            for (int i = 0; i < 8; ++i) wr[i] = Ws[k][ty + i * 16];
            #pragma unroll
            for (int j = 0; j < 4; ++j) yr[j] = Ys[k][tx + j * 16];
            #pragma unroll
            for (int i = 0; i < 8; ++i)
                #pragma unroll
                for (int j = 0; j < 4; ++j)
                    acc[i][j] = fmaf(wr[i], yr[j], acc[i][j]);
        }
    }

    float* __restrict__ outn = out + (size_t)n * COUT * HW;

    #pragma unroll
    for (int i = 0; i < 8; ++i) {
        const int o = o0 + ty + i * 16;
        const float a2  = __ldg(&g2[o]) * rsqrtf(__ldg(&v2[o]) + EPSV);
        const float sh2 = __ldg(&b2a[o]) - __ldg(&m2[o]) * a2 + __ldg(&pb[o]) * a2;
        float lm = 0.f;
        #pragma unroll
        for (int j = 0; j < 4; ++j) {
            float z = fmaxf(fmaf(acc[i][j], a2, sh2), 0.f);
            outn[(size_t)o * HW + hw0 + tx + j * 16] = z;
            lm = fmaxf(lm, z);
        }
        atomicMax(&smaxb[ty + i * 16], __float_as_int(lm));
    }
    __syncthreads();
    if (tid < 128)
        atomicMax(&g_zmax[n * COUT + o0 + tid], smaxb[tid]);
}

// ---------------------------------------------------------------------------
// K3: apply pointwise cut — zero planes whose max < 1e-3
// ---------------------------------------------------------------------------
__global__ __launch_bounds__(256)
void k_cut(float* __restrict__ out)
{
    const int plane = blockIdx.x;   // n*COUT + o
    if (__int_as_float(g_zmax[plane]) >= PW_TH) return;
    float* __restrict__ p = out + (size_t)plane * HW;
    for (int i = threadIdx.x; i < HW; i += 256) p[i] = 0.f;
}

// ---------------------------------------------------------------------------
extern "C" void kernel_launch(void* const* d_in, const int* in_sizes, int n_in,
                              void* d_out, int out_size)
{
    const float* x    = (const float*)d_in[0];
    const float* dww  = (const float*)d_in[1];
    const float* dwb  = (const float*)d_in[2];
    const float* g1   = (const float*)d_in[3];
    const float* b1   = (const float*)d_in[4];
    const float* m1   = (const float*)d_in[5];
    const float* v1   = (const float*)d_in[6];
    const float* pw   = (const float*)d_in[7];
    const float* pb   = (const float*)d_in[8];
    const float* g2   = (const float*)d_in[9];
    const float* b2   = (const float*)d_in[10];
    const float* m2   = (const float*)d_in[11];
    const float* v2   = (const float*)d_in[12];
    float* out = (float*)d_out;

    k_zero_max<<<(N_ * COUT + 255) / 256, 256>>>();
    k_dw<<<N_ * CIN, 256>>>(x, dww, dwb, g1, b1, m1, v1);
    dim3 grid(HW / 64, COUT / 128, N_);   // 49 x 4 x 32
    k_pw<<<grid, 256>>>(pw, pb, g2, b2, m2, v2, out);
    k_cut<<<N_ * COUT, 256>>>(out);
}

// round 3
// speedup vs baseline: 2.5842x; 2.5842x over previous
#include <cuda_runtime.h>
#include <cuda_bf16.h>
#include <cstdint>

#define N_    32
#define CIN   256
#define COUT  512
#define HW    3136
#define EPSV  1e-5f
#define DW_TH 4.0f
#define PW_TH 1e-3f

// GEMM tiling: CTA tile 64(hw) x 128(o), K chunks of 64, 2-stage cp.async pipe
#define TM_HW  64
#define TN_O   128
#define KC     64
#define NKC    (CIN / KC)          // 4
// smem stage layout (rows padded to 144B for conflict-free ldmatrix)
#define YROW   144
#define WROW   144
#define YHSZ   (TM_HW * YROW)      // 9216 per half (rows = k, 64 rows? no: rows=KC)
#define OFF_YHI 0
#define OFF_YLO (KC * YROW)                    // 9216
#define OFF_WHI (2 * KC * YROW)                // 18432
#define OFF_WLO (2 * KC * YROW + TN_O * WROW)  // 36864
#define STAGE   (2 * KC * YROW + 2 * TN_O * WROW)   // 55296
#define OFF_EPI (2 * STAGE)                    // 110592
#define SMEM_PW (OFF_EPI + TN_O * 12)          // +a2s/sh2s/smax = 112128

// ---------------- scratch (no allocs allowed) ----------------
__device__ __align__(16) __nv_bfloat16 g_yhi[(size_t)N_ * CIN * HW];
__device__ __align__(16) __nv_bfloat16 g_ylo[(size_t)N_ * CIN * HW];
__device__ __align__(16) __nv_bfloat16 g_whi[COUT * CIN];
__device__ __align__(16) __nv_bfloat16 g_wlo[COUT * CIN];
__device__ int g_zmax[N_ * COUT];

// ---------------- helpers ----------------
__device__ __forceinline__ uint32_t smem_u32(const void* p) {
    uint32_t a;
    asm("{ .reg .u64 t; cvta.to.shared.u64 t, %1; cvt.u32.u64 %0, t; }" : "=r"(a) : "l"(p));
    return a;
}
__device__ __forceinline__ void cp16(uint32_t saddr, const void* g) {
    asm volatile("cp.async.cg.shared.global [%0], [%1], 16;" :: "r"(saddr), "l"(g));
}
#define CP_COMMIT() asm volatile("cp.async.commit_group;" ::: "memory")
#define CP_WAIT1()  asm volatile("cp.async.wait_group 1;" ::: "memory")
#define CP_WAIT0()  asm volatile("cp.async.wait_group 0;" ::: "memory")

__device__ __forceinline__ void ldsm4(uint32_t* r, uint32_t a) {
    asm volatile("ldmatrix.sync.aligned.m8n8.x4.shared.b16 {%0,%1,%2,%3}, [%4];"
                 : "=r"(r[0]), "=r"(r[1]), "=r"(r[2]), "=r"(r[3]) : "r"(a));
}
__device__ __forceinline__ void ldsm4t(uint32_t* r, uint32_t a) {
    asm volatile("ldmatrix.sync.aligned.m8n8.x4.trans.shared.b16 {%0,%1,%2,%3}, [%4];"
                 : "=r"(r[0]), "=r"(r[1]), "=r"(r[2]), "=r"(r[3]) : "r"(a));
}
__device__ __forceinline__ void mma_bf16(float* c, const uint32_t* a, uint32_t b0, uint32_t b1) {
    asm volatile("mma.sync.aligned.m16n8k16.row.col.f32.bf16.bf16.f32 "
                 "{%0,%1,%2,%3}, {%4,%5,%6,%7}, {%8,%9}, {%0,%1,%2,%3};"
                 : "+f"(c[0]), "+f"(c[1]), "+f"(c[2]), "+f"(c[3])
                 : "r"(a[0]), "r"(a[1]), "r"(a[2]), "r"(a[3]), "r"(b0), "r"(b1));
}

// ---------------------------------------------------------------------------
__global__ void k_zero_max() {
    int i = blockIdx.x * blockDim.x + threadIdx.x;
    if (i < N_ * COUT) g_zmax[i] = 0;
}

// split W fp32 -> bf16 hi/lo
__global__ void k_prep(const float* __restrict__ pw) {
    int i = blockIdx.x * blockDim.x + threadIdx.x;
    float w = pw[i];
    __nv_bfloat16 h = __float2bfloat16(w);
    g_whi[i] = h;
    g_wlo[i] = __float2bfloat16(w - __bfloat162float(h));
}

// ---------------------------------------------------------------------------
// K1: depthwise 3x3 + bias + BN1 + ReLU + per-plane cut; writes bf16 hi/lo
// ---------------------------------------------------------------------------
__global__ __launch_bounds__(256)
void k_dw(const float* __restrict__ x,
          const float* __restrict__ dww,  const float* __restrict__ dwb,
          const float* __restrict__ g1,   const float* __restrict__ b1,
          const float* __restrict__ m1,   const float* __restrict__ v1)
{
    __shared__ float sx[58 * 58];
    __shared__ float sy[HW];
    __shared__ float smax[256];

    const int bid = blockIdx.x;            // n*CIN + c
    const int c   = bid & (CIN - 1);
    const int tid = threadIdx.x;
    const float* __restrict__ xp = x + (size_t)bid * HW;

    for (int i = tid; i < 58 * 58; i += 256) {
        int r = i / 58, q = i - r * 58;
        int gh = r - 1, gw = q - 1;
        float v = 0.f;
        if ((unsigned)gh < 56u && (unsigned)gw < 56u) v = xp[gh * 56 + gw];
        sx[i] = v;
    }

    const float w0 = __ldg(&dww[c*9+0]), w1 = __ldg(&dww[c*9+1]), w2 = __ldg(&dww[c*9+2]);
    const float w3 = __ldg(&dww[c*9+3]), w4 = __ldg(&dww[c*9+4]), w5 = __ldg(&dww[c*9+5]);
    const float w6 = __ldg(&dww[c*9+6]), w7 = __ldg(&dww[c*9+7]), w8 = __ldg(&dww[c*9+8]);
    const float a  = __ldg(&g1[c]) * rsqrtf(__ldg(&v1[c]) + EPSV);
    const float sh = __ldg(&b1[c]) - __ldg(&m1[c]) * a + __ldg(&dwb[c]) * a;

    __syncthreads();

    float lmax = 0.f;
    for (int i = tid; i < HW; i += 256) {
        int h = i / 56, w = i - h * 56;
        const float* p = &sx[h * 58 + w];
        float acc = p[0]   * w0 + p[1]   * w1 + p[2]   * w2
                  + p[58]  * w3 + p[59]  * w4 + p[60]  * w5
                  + p[116] * w6 + p[117] * w7 + p[118] * w8;
        float val = fmaxf(fmaf(acc, a, sh), 0.f);
        sy[i] = val;
        lmax = fmaxf(lmax, val);
    }
    smax[tid] = lmax;
    __syncthreads();
    #pragma unroll
    for (int s = 128; s > 0; s >>= 1) {
        if (tid < s) smax[tid] = fmaxf(smax[tid], smax[tid + s]);
        __syncthreads();
    }
    const bool cut = smax[0] < DW_TH;

    __nv_bfloat16* __restrict__ yh = g_yhi + (size_t)bid * HW;
    __nv_bfloat16* __restrict__ yl = g_ylo + (size_t)bid * HW;
    for (int i = tid; i < HW; i += 256) {
        float v = cut ? 0.f : sy[i];
        __nv_bfloat16 h = __float2bfloat16(v);
        yh[i] = h;
        yl[i] = __float2bfloat16(v - __bfloat162float(h));
    }
}

// ---------------------------------------------------------------------------
// K2: mma.sync bf16 3-pass GEMM.
// D[hw,o] = Yhi.Whi + Yhi.Wlo + Ylo.Whi ; A=Y via ldmatrix.trans (col-major),
// B=W via ldmatrix. Fused BN2 + ReLU + per-(n,o) max.
// ---------------------------------------------------------------------------
__global__ __launch_bounds__(256, 2)
void k_pw(const float* __restrict__ pb,
          const float* __restrict__ g2,  const float* __restrict__ b2v,
          const float* __restrict__ m2,  const float* __restrict__ v2,
          float* __restrict__ out)
{
    extern __shared__ char smem[];
    const uint32_t sb = smem_u32(smem);
    const int tid  = threadIdx.x;
    const int wid  = tid >> 5;
    const int lane = tid & 31;
    const int wm   = wid & 1;          // 2 m-warps (hw)
    const int wn   = wid >> 1;         // 4 n-warps (o)
    const int qg   = lane >> 3;        // ldmatrix quad
    const int rr   = lane & 7;
    const int g    = lane >> 2;        // mma row group
    const int t    = lane & 3;

    const int hw0 = blockIdx.x * TM_HW;    // 49
    const int o0  = blockIdx.y * TN_O;     // 4
    const int n   = blockIdx.z;            // 32

    // epilogue params
    float* a2s  = (float*)(smem + OFF_EPI);
    float* sh2s = (float*)(smem + OFF_EPI + TN_O * 4);
    int*   smax = (int*)  (smem + OFF_EPI + TN_O * 8);
    if (tid < TN_O) {
        const int o = o0 + tid;
        float a2 = __ldg(&g2[o]) * rsqrtf(__ldg(&v2[o]) + EPSV);
        a2s[tid]  = a2;
        sh2s[tid] = __ldg(&b2v[o]) - __ldg(&m2[o]) * a2 + __ldg(&pb[o]) * a2;
        smax[tid] = 0;
    }

    const __nv_bfloat16* __restrict__ ynh = g_yhi + (size_t)n * CIN * HW;
    const __nv_bfloat16* __restrict__ ynl = g_ylo + (size_t)n * CIN * HW;

    // ---- stage fill ----
    auto fill = [&](int st, int ck) {
        const uint32_t s0 = sb + st * STAGE;
        const int k0 = ck * KC;
        #pragma unroll
        for (int it = 0; it < 2; ++it) {           // Y: KC rows x 128B per half
            int idx = tid + it * 256;
            int row = idx >> 3, ch = idx & 7;
            size_t go = (size_t)(k0 + row) * HW + hw0 + ch * 8;
            uint32_t so = row * YROW + ch * 16;
            cp16(s0 + OFF_YHI + so, ynh + go);
            cp16(s0 + OFF_YLO + so, ynl + go);
        }
        #pragma unroll
        for (int it = 0; it < 4; ++it) {           // W: TN_O rows x 128B per half
            int idx = tid + it * 256;
            int row = idx >> 3, ch = idx & 7;
            size_t go = (size_t)(o0 + row) * CIN + k0 + ch * 8;
            uint32_t so = row * WROW + ch * 16;
            cp16(s0 + OFF_WHI + so, g_whi + go);
            cp16(s0 + OFF_WLO + so, g_wlo + go);
        }
    };

    float acc[2][4][4];
    #pragma unroll
    for (int i = 0; i < 2; ++i)
        #pragma unroll
        for (int j = 0; j < 4; ++j)
            #pragma unroll
            for (int r = 0; r < 4; ++r) acc[i][j][r] = 0.f;

    fill(0, 0); CP_COMMIT();
    fill(1, 1); CP_COMMIT();

    // invariant parts of ldmatrix addresses
    // A (trans): row k = s*16 + (q>>1)*8 + rr ; col byte = (wm*32 + i*16 + (q&1)*8)*2
    const uint32_t aRow = ((qg >> 1) * 8 + rr);
    const uint32_t aColB = (wm * 32 + (qg & 1) * 8) * 2;
    // B: row o = wn*32 + jp*16 + (q>>1)*8 + rr ; col byte = (s*16 + (q&1)*8)*2
    const uint32_t bRow = (wn * 32 + (qg >> 1) * 8 + rr);
    const uint32_t bColB = ((qg & 1) * 8) * 2;

    for (int ck = 0; ck < NKC; ++ck) {
        if (ck < NKC - 1) CP_WAIT1(); else CP_WAIT0();
        __syncthreads();
        const uint32_t s0 = sb + (ck & 1) * STAGE;
        const uint32_t yhB = s0 + OFF_YHI, ylB = s0 + OFF_YLO;
        const uint32_t whB = s0 + OFF_WHI, wlB = s0 + OFF_WLO;

        #pragma unroll
        for (int s = 0; s < KC / 16; ++s) {
            uint32_t bh[2][4], bl[2][4];
            #pragma unroll
            for (int jp = 0; jp < 2; ++jp) {
                uint32_t ro = (bRow + jp * 16) * WROW + bColB + s * 32;
                ldsm4(bh[jp], whB + ro);
                ldsm4(bl[jp], wlB + ro);
            }
            #pragma unroll
            for (int i = 0; i < 2; ++i) {
                uint32_t ah[4], al[4];
                uint32_t ro = (s * 16 + aRow) * YROW + aColB + i * 32;
                ldsm4t(ah, yhB + ro);
                ldsm4t(al, ylB + ro);
                #pragma unroll
                for (int jp = 0; jp < 2; ++jp) {
                    #pragma unroll
                    for (int jj = 0; jj < 2; ++jj) {
                        float* c = acc[i][jp * 2 + jj];
                        uint32_t B0 = bh[jp][jj * 2], B1 = bh[jp][jj * 2 + 1];
                        mma_bf16(c, ah, B0, B1);                       // Yhi.Whi
                        mma_bf16(c, al, B0, B1);                       // Ylo.Whi
                        mma_bf16(c, ah, bl[jp][jj * 2], bl[jp][jj * 2 + 1]); // Yhi.Wlo
                    }
                }
            }
        }
        __syncthreads();
        if (ck + 2 < NKC) { fill(ck & 1, ck + 2); CP_COMMIT(); }
    }

    // ---- epilogue ----
    float* __restrict__ outn = out + (size_t)n * COUT * HW;
    #pragma unroll
    for (int i = 0; i < 2; ++i) {
        const int hwa = hw0 + wm * 32 + i * 16 + g;
        #pragma unroll
        for (int j = 0; j < 4; ++j) {
            const int col = wn * 32 + j * 8 + t * 2;   // o within tile
            const int o   = o0 + col;
            const float a20 = a2s[col],     sh0 = sh2s[col];
            const float a21 = a2s[col + 1], sh1 = sh2s[col + 1];
            float z0 = fmaxf(fmaf(acc[i][j][0], a20, sh0), 0.f);
            float z1 = fmaxf(fmaf(acc[i][j][1], a21, sh1), 0.f);
            float z2 = fmaxf(fmaf(acc[i][j][2], a20, sh0), 0.f);
            float z3 = fmaxf(fmaf(acc[i][j][3], a21, sh1), 0.f);
            outn[(size_t)o * HW + hwa]           = z0;
            outn[(size_t)(o + 1) * HW + hwa]     = z1;
            outn[(size_t)o * HW + hwa + 8]       = z2;
            outn[(size_t)(o + 1) * HW + hwa + 8] = z3;
            atomicMax(&smax[col],     __float_as_int(fmaxf(z0, z2)));
            atomicMax(&smax[col + 1], __float_as_int(fmaxf(z1, z3)));
        }
    }
    __syncthreads();
    if (tid < TN_O)
        atomicMax(&g_zmax[n * COUT + o0 + tid], smax[tid]);
}

// ---------------------------------------------------------------------------
// K3: zero planes whose max < 1e-3
// ---------------------------------------------------------------------------
__global__ __launch_bounds__(256)
void k_cut(float* __restrict__ out)
{
    const int base = blockIdx.x * 8;
    for (int p = 0; p < 8; ++p) {
        const int plane = base + p;
        if (__int_as_float(g_zmax[plane]) >= PW_TH) continue;
        float* __restrict__ q = out + (size_t)plane * HW;
        for (int i = threadIdx.x; i < HW; i += 256) q[i] = 0.f;
    }
}

// ---------------------------------------------------------------------------
extern "C" void kernel_launch(void* const* d_in, const int* in_sizes, int n_in,
                              void* d_out, int out_size)
{
    const float* x    = (const float*)d_in[0];
    const float* dww  = (const float*)d_in[1];
    const float* dwb  = (const float*)d_in[2];
    const float* g1   = (const float*)d_in[3];
    const float* b1   = (const float*)d_in[4];
    const float* m1   = (const float*)d_in[5];
    const float* v1   = (const float*)d_in[6];
    const float* pw   = (const float*)d_in[7];
    const float* pb   = (const float*)d_in[8];
    const float* g2   = (const float*)d_in[9];
    const float* b2   = (const float*)d_in[10];
    const float* m2   = (const float*)d_in[11];
    const float* v2   = (const float*)d_in[12];
    float* out = (float*)d_out;

    static int attr_done = 0;
    cudaFuncSetAttribute(k_pw, cudaFuncAttributeMaxDynamicSharedMemorySize, SMEM_PW);
    (void)attr_done;

    k_zero_max<<<(N_ * COUT + 255) / 256, 256>>>();
    k_prep<<<(COUT * CIN) / 256, 256>>>(pw);
    k_dw<<<N_ * CIN, 256>>>(x, dww, dwb, g1, b1, m1, v1);
    dim3 grid(HW / TM_HW, COUT / TN_O, N_);   // 49 x 4 x 32
    k_pw<<<grid, 256, SMEM_PW>>>(pb, g2, b2, m2, v2, out);
    k_cut<<<(N_ * COUT) / 8, 256>>>(out);
}

// round 4
// speedup vs baseline: 3.2423x; 1.2547x over previous
#include <cuda_runtime.h>
#include <cuda_fp16.h>
#include <cstdint>

#define N_    32
#define CIN   256
#define COUT  512
#define HW    3136
#define EPSV  1e-5f
#define DW_TH 4.0f
#define PW_TH 1e-3f

// GEMM tiling: CTA 64(hw) x 128(o), K chunks of 32, 4-stage cp.async pipe
#define TM_HW  64
#define TN_O   128
#define KC     32
#define NKC    (CIN / KC)          // 8
#define NST    4
// smem stage layout
#define YROW   144                 // 64 hw * 2B = 128B + 16 pad
#define WROW   80                  // 32 k  * 2B = 64B  + 16 pad
#define OFF_Y  0
#define OFF_WH (KC * YROW)                   // 4608
#define OFF_WL (KC * YROW + TN_O * WROW)     // 14848
#define STAGE  (KC * YROW + 2 * TN_O * WROW) // 25088
#define OFF_EPI (NST * STAGE)                // 100352
#define SMEM_PW (OFF_EPI + TN_O * 12)        // 101888

// ---------------- scratch (no allocs allowed) ----------------
__device__ __align__(16) __half g_yh[(size_t)N_ * CIN * HW];   // 51.5 MB
__device__ __align__(16) __half g_wh[COUT * CIN];
__device__ __align__(16) __half g_wl[COUT * CIN];
__device__ int g_zmax[N_ * COUT];

// ---------------- helpers ----------------
__device__ __forceinline__ uint32_t smem_u32(const void* p) {
    uint32_t a;
    asm("{ .reg .u64 t; cvta.to.shared.u64 t, %1; cvt.u32.u64 %0, t; }" : "=r"(a) : "l"(p));
    return a;
}
__device__ __forceinline__ void cp16(uint32_t saddr, const void* g) {
    asm volatile("cp.async.cg.shared.global [%0], [%1], 16;" :: "r"(saddr), "l"(g));
}
#define CP_COMMIT() asm volatile("cp.async.commit_group;" ::: "memory")
#define CP_WAIT2()  asm volatile("cp.async.wait_group 2;" ::: "memory")

__device__ __forceinline__ void ldsm4(uint32_t* r, uint32_t a) {
    asm volatile("ldmatrix.sync.aligned.m8n8.x4.shared.b16 {%0,%1,%2,%3}, [%4];"
                 : "=r"(r[0]), "=r"(r[1]), "=r"(r[2]), "=r"(r[3]) : "r"(a));
}
__device__ __forceinline__ void ldsm4t(uint32_t* r, uint32_t a) {
    asm volatile("ldmatrix.sync.aligned.m8n8.x4.trans.shared.b16 {%0,%1,%2,%3}, [%4];"
                 : "=r"(r[0]), "=r"(r[1]), "=r"(r[2]), "=r"(r[3]) : "r"(a));
}
__device__ __forceinline__ void mma_f16(float* c, const uint32_t* a, uint32_t b0, uint32_t b1) {
    asm volatile("mma.sync.aligned.m16n8k16.row.col.f32.f16.f16.f32 "
                 "{%0,%1,%2,%3}, {%4,%5,%6,%7}, {%8,%9}, {%0,%1,%2,%3};"
                 : "+f"(c[0]), "+f"(c[1]), "+f"(c[2]), "+f"(c[3])
                 : "r"(a[0]), "r"(a[1]), "r"(a[2]), "r"(a[3]), "r"(b0), "r"(b1));
}

// ---------------------------------------------------------------------------
// k_prep: split W fp32 -> fp16 hi/lo ; also zeros g_zmax
// ---------------------------------------------------------------------------
__global__ void k_prep(const float* __restrict__ pw) {
    int i = blockIdx.x * blockDim.x + threadIdx.x;   // COUT*CIN = 131072
    float w = pw[i];
    __half h = __float2half_rn(w);
    g_wh[i] = h;
    g_wl[i] = __float2half_rn(w - __half2float(h));
    if (i < N_ * COUT) g_zmax[i] = 0;
}

// ---------------------------------------------------------------------------
// K1: depthwise 3x3 + bias + BN1 + ReLU + per-plane cut; writes fp16
// 224 threads, 14 outputs per thread held in registers.
// ---------------------------------------------------------------------------
__global__ __launch_bounds__(224)
void k_dw(const float* __restrict__ x,
          const float* __restrict__ dww,  const float* __restrict__ dwb,
          const float* __restrict__ g1,   const float* __restrict__ b1,
          const float* __restrict__ m1,   const float* __restrict__ v1)
{
    __shared__ float sx[58 * 58];
    __shared__ float wmax[8];

    const int bid = blockIdx.x;            // n*CIN + c
    const int c   = bid & (CIN - 1);
    const int tid = threadIdx.x;
    const float* __restrict__ xp = x + (size_t)bid * HW;

    for (int i = tid; i < 58 * 58; i += 224) {
        int r = i / 58, q = i - r * 58;
        int gh = r - 1, gw = q - 1;
        float v = 0.f;
        if ((unsigned)gh < 56u && (unsigned)gw < 56u) v = xp[gh * 56 + gw];
        sx[i] = v;
    }

    const float ww0 = __ldg(&dww[c*9+0]), ww1 = __ldg(&dww[c*9+1]), ww2 = __ldg(&dww[c*9+2]);
    const float ww3 = __ldg(&dww[c*9+3]), ww4 = __ldg(&dww[c*9+4]), ww5 = __ldg(&dww[c*9+5]);
    const float ww6 = __ldg(&dww[c*9+6]), ww7 = __ldg(&dww[c*9+7]), ww8 = __ldg(&dww[c*9+8]);
    const float a  = __ldg(&g1[c]) * rsqrtf(__ldg(&v1[c]) + EPSV);
    const float sh = __ldg(&b1[c]) - __ldg(&m1[c]) * a + __ldg(&dwb[c]) * a;

    __syncthreads();

    float v[14];
    float lmax = 0.f;
    const int h0 = tid / 56;               // 0..3
    const int w0 = tid - h0 * 56;
    const float* p = sx + h0 * 58 + w0;
    #pragma unroll
    for (int j = 0; j < 14; ++j) {
        float acc = p[0]   * ww0 + p[1]   * ww1 + p[2]   * ww2
                  + p[58]  * ww3 + p[59]  * ww4 + p[60]  * ww5
                  + p[116] * ww6 + p[117] * ww7 + p[118] * ww8;
        v[j] = fmaxf(fmaf(acc, a, sh), 0.f);
        lmax = fmaxf(lmax, v[j]);
        p += 4 * 58;
    }
    #pragma unroll
    for (int o = 16; o; o >>= 1) lmax = fmaxf(lmax, __shfl_xor_sync(~0u, lmax, o));
    if ((tid & 31) == 0) wmax[tid >> 5] = lmax;
    __syncthreads();
    if (tid == 0) {
        float m = wmax[0];
        #pragma unroll
        for (int i = 1; i < 7; ++i) m = fmaxf(m, wmax[i]);
        wmax[0] = m;
    }
    __syncthreads();
    const bool cut = wmax[0] < DW_TH;

    __half* __restrict__ yp = g_yh + (size_t)bid * HW;
    #pragma unroll
    for (int j = 0; j < 14; ++j)
        yp[tid + j * 224] = __float2half_rn(cut ? 0.f : v[j]);
}

// ---------------------------------------------------------------------------
// K2: mma.sync fp16 2-pass GEMM: D = Y.Whi + Y.Wlo (Y single fp16).
// 4-stage cp.async pipeline, KC=32. Fused BN2 + ReLU + per-(n,o) max.
// ---------------------------------------------------------------------------
__global__ __launch_bounds__(256, 2)
void k_pw(const float* __restrict__ pb,
          const float* __restrict__ g2,  const float* __restrict__ b2v,
          const float* __restrict__ m2,  const float* __restrict__ v2,
          float* __restrict__ out)
{
    extern __shared__ char smem[];
    const uint32_t sb = smem_u32(smem);
    const int tid  = threadIdx.x;
    const int wid  = tid >> 5;
    const int lane = tid & 31;
    const int wm   = wid & 1;          // 2 m-warps (hw, 32 each)
    const int wn   = wid >> 1;         // 4 n-warps (o, 32 each)
    const int qg   = lane >> 3;
    const int rr   = lane & 7;
    const int g    = lane >> 2;
    const int t    = lane & 3;

    const int hw0 = blockIdx.x * TM_HW;    // 49
    const int o0  = blockIdx.y * TN_O;     // 4
    const int n   = blockIdx.z;            // 32

    float* a2s  = (float*)(smem + OFF_EPI);
    float* sh2s = (float*)(smem + OFF_EPI + TN_O * 4);
    int*   smax = (int*)  (smem + OFF_EPI + TN_O * 8);
    if (tid < TN_O) {
        const int o = o0 + tid;
        float a2 = __ldg(&g2[o]) * rsqrtf(__ldg(&v2[o]) + EPSV);
        a2s[tid]  = a2;
        sh2s[tid] = __ldg(&b2v[o]) - __ldg(&m2[o]) * a2 + __ldg(&pb[o]) * a2;
        smax[tid] = 0;
    }

    const __half* __restrict__ yn = g_yh + (size_t)n * CIN * HW;

    auto fill = [&](int slot, int ck) {
        const uint32_t s0 = sb + slot * STAGE;
        const int k0 = ck * KC;
        {   // Y: 32 rows x 8 chunks = 256
            int row = tid >> 3, ch = tid & 7;
            cp16(s0 + OFF_Y + row * YROW + ch * 16,
                 yn + (size_t)(k0 + row) * HW + hw0 + ch * 8);
        }
        #pragma unroll
        for (int it = 0; it < 2; ++it) {   // W hi+lo: 128 rows x 4 chunks = 512 each
            int idx = tid + it * 256;
            int row = idx >> 2, ch = idx & 3;
            size_t go = (size_t)(o0 + row) * CIN + k0 + ch * 8;
            uint32_t so = row * WROW + ch * 16;
            cp16(s0 + OFF_WH + so, g_wh + go);
            cp16(s0 + OFF_WL + so, g_wl + go);
        }
    };

    float acc[2][4][4];
    #pragma unroll
    for (int i = 0; i < 2; ++i)
        #pragma unroll
        for (int j = 0; j < 4; ++j)
            #pragma unroll
            for (int r = 0; r < 4; ++r) acc[i][j][r] = 0.f;

    fill(0, 0); CP_COMMIT();
    fill(1, 1); CP_COMMIT();
    fill(2, 2); CP_COMMIT();

    // A (Y, trans): row = s*16 + aRow ; col byte = wm*64 + (qg&1)*16 + i*32
    const uint32_t aRow  = (qg >> 1) * 8 + rr;
    const uint32_t aColB = wm * 64 + (qg & 1) * 16;
    // B (W): row = wn*32 + jp*16 + (qg>>1)*8 + rr ; col byte = s*32 + (qg&1)*16
    const uint32_t bRow  = wn * 32 + (qg >> 1) * 8 + rr;
    const uint32_t bColB = (qg & 1) * 16;

    for (int ck = 0; ck < NKC; ++ck) {
        CP_WAIT2();
        __syncthreads();
        const uint32_t s0  = sb + (ck & 3) * STAGE;
        const uint32_t yB  = s0 + OFF_Y;
        const uint32_t whB = s0 + OFF_WH;
        const uint32_t wlB = s0 + OFF_WL;

        #pragma unroll
        for (int s = 0; s < KC / 16; ++s) {
            uint32_t bh[2][4], bl[2][4];
            #pragma unroll
            for (int jp = 0; jp < 2; ++jp) {
                uint32_t ro = (bRow + jp * 16) * WROW + bColB + s * 32;
                ldsm4(bh[jp], whB + ro);
                ldsm4(bl[jp], wlB + ro);
            }
            #pragma unroll
            for (int i = 0; i < 2; ++i) {
                uint32_t av[4];
                ldsm4t(av, yB + (s * 16 + aRow) * YROW + aColB + i * 32);
                #pragma unroll
                for (int jp = 0; jp < 2; ++jp) {
                    #pragma unroll
                    for (int jj = 0; jj < 2; ++jj) {
                        float* c = acc[i][jp * 2 + jj];
                        mma_f16(c, av, bh[jp][jj * 2], bh[jp][jj * 2 + 1]);
                        mma_f16(c, av, bl[jp][jj * 2], bl[jp][jj * 2 + 1]);
                    }
                }
            }
        }
        if (ck + 3 < NKC) fill((ck + 3) & 3, ck + 3);
        CP_COMMIT();
    }

    // ---- epilogue ----
    float* __restrict__ outn = out + (size_t)n * COUT * HW;
    #pragma unroll
    for (int i = 0; i < 2; ++i) {
        const int hwa = hw0 + wm * 32 + i * 16 + g;
        #pragma unroll
        for (int j = 0; j < 4; ++j) {
            const int col = wn * 32 + j * 8 + t * 2;
            const int o   = o0 + col;
            const float a20 = a2s[col],     sh0 = sh2s[col];
            const float a21 = a2s[col + 1], sh1 = sh2s[col + 1];
            float z0 = fmaxf(fmaf(acc[i][j][0], a20, sh0), 0.f);
            float z1 = fmaxf(fmaf(acc[i][j][1], a21, sh1), 0.f);
            float z2 = fmaxf(fmaf(acc[i][j][2], a20, sh0), 0.f);
            float z3 = fmaxf(fmaf(acc[i][j][3], a21, sh1), 0.f);
            outn[(size_t)o * HW + hwa]           = z0;
            outn[(size_t)(o + 1) * HW + hwa]     = z1;
            outn[(size_t)o * HW + hwa + 8]       = z2;
            outn[(size_t)(o + 1) * HW + hwa + 8] = z3;
            atomicMax(&smax[col],     __float_as_int(fmaxf(z0, z2)));
            atomicMax(&smax[col + 1], __float_as_int(fmaxf(z1, z3)));
        }
    }
    __syncthreads();
    if (tid < TN_O)
        atomicMax(&g_zmax[n * COUT + o0 + tid], smax[tid]);
}

// ---------------------------------------------------------------------------
// K3: zero planes whose max < 1e-3
// ---------------------------------------------------------------------------
__global__ __launch_bounds__(256)
void k_cut(float* __restrict__ out)
{
    const int base = blockIdx.x * 8;
    for (int p = 0; p < 8; ++p) {
        const int plane = base + p;
        if (__int_as_float(g_zmax[plane]) >= PW_TH) continue;
        float* __restrict__ q = out + (size_t)plane * HW;
        for (int i = threadIdx.x; i < HW; i += 256) q[i] = 0.f;
    }
}

// ---------------------------------------------------------------------------
extern "C" void kernel_launch(void* const* d_in, const int* in_sizes, int n_in,
                              void* d_out, int out_size)
{
    const float* x    = (const float*)d_in[0];
    const float* dww  = (const float*)d_in[1];
    const float* dwb  = (const float*)d_in[2];
    const float* g1   = (const float*)d_in[3];
    const float* b1   = (const float*)d_in[4];
    const float* m1   = (const float*)d_in[5];
    const float* v1   = (const float*)d_in[6];
    const float* pw   = (const float*)d_in[7];
    const float* pb   = (const float*)d_in[8];
    const float* g2   = (const float*)d_in[9];
    const float* b2   = (const float*)d_in[10];
    const float* m2   = (const float*)d_in[11];
    const float* v2   = (const float*)d_in[12];
    float* out = (float*)d_out;

    cudaFuncSetAttribute(k_pw, cudaFuncAttributeMaxDynamicSharedMemorySize, SMEM_PW);

    k_prep<<<(COUT * CIN) / 256, 256>>>(pw);
    k_dw<<<N_ * CIN, 224>>>(x, dww, dwb, g1, b1, m1, v1);
    dim3 grid(HW / TM_HW, COUT / TN_O, N_);   // 49 x 4 x 32
    k_pw<<<grid, 256, SMEM_PW>>>(pb, g2, b2, m2, v2, out);
    k_cut<<<(N_ * COUT) / 8, 256>>>(out);
}

// round 6
// speedup vs baseline: 3.9454x; 1.2169x over previous
#include <cuda_runtime.h>
#include <cuda_fp16.h>
#include <cstdint>

#define N_    32
#define CIN   256
#define COUT  512
#define HW    3136
#define EPSV  1e-5f
#define DW_TH 4.0f
#define PW_TH 1e-3f

// GEMM tiling: CTA 64(hw) x 128(o), K chunks of 32, 4-stage cp.async pipe
#define TM_HW  64
#define TN_O   128
#define KC     32
#define NKC    (CIN / KC)          // 8
#define NST    4
// smem stage layout
#define YROW   144                 // 64 hw * 2B = 128B + 16 pad
#define WROW   80                  // 32 k  * 2B = 64B  + 16 pad
#define OFF_Y  0
#define OFF_W  (KC * YROW)                   // 4608
#define STAGE  (KC * YROW + TN_O * WROW)     // 14848
#define OFF_EPI (NST * STAGE)                // 59392
#define SMEM_PW (OFF_EPI + TN_O * 12)        // 60928

// ---------------- scratch (no allocs allowed) ----------------
__device__ __align__(16) __half g_yh[(size_t)N_ * CIN * HW];   // 51.5 MB
__device__ __align__(16) __half g_wh[COUT * CIN];
__device__ int g_zmax[N_ * COUT];

// ---------------- helpers ----------------
__device__ __forceinline__ uint32_t smem_u32(const void* p) {
    uint32_t a;
    asm("{ .reg .u64 t; cvta.to.shared.u64 t, %1; cvt.u32.u64 %0, t; }" : "=r"(a) : "l"(p));
    return a;
}
__device__ __forceinline__ void cp16(uint32_t saddr, const void* g) {
    asm volatile("cp.async.cg.shared.global [%0], [%1], 16;" :: "r"(saddr), "l"(g));
}
#define CP_COMMIT() asm volatile("cp.async.commit_group;" ::: "memory")
#define CP_WAIT2()  asm volatile("cp.async.wait_group 2;" ::: "memory")

__device__ __forceinline__ void ldsm4(uint32_t* r, uint32_t a) {
    asm volatile("ldmatrix.sync.aligned.m8n8.x4.shared.b16 {%0,%1,%2,%3}, [%4];"
                 : "=r"(r[0]), "=r"(r[1]), "=r"(r[2]), "=r"(r[3]) : "r"(a));
}
__device__ __forceinline__ void ldsm4t(uint32_t* r, uint32_t a) {
    asm volatile("ldmatrix.sync.aligned.m8n8.x4.trans.shared.b16 {%0,%1,%2,%3}, [%4];"
                 : "=r"(r[0]), "=r"(r[1]), "=r"(r[2]), "=r"(r[3]) : "r"(a));
}
__device__ __forceinline__ void mma_f16(float* c, const uint32_t* a, uint32_t b0, uint32_t b1) {
    asm volatile("mma.sync.aligned.m16n8k16.row.col.f32.f16.f16.f32 "
                 "{%0,%1,%2,%3}, {%4,%5,%6,%7}, {%8,%9}, {%0,%1,%2,%3};"
                 : "+f"(c[0]), "+f"(c[1]), "+f"(c[2]), "+f"(c[3])
                 : "r"(a[0]), "r"(a[1]), "r"(a[2]), "r"(a[3]), "r"(b0), "r"(b1));
}

// ---------------------------------------------------------------------------
// k_prep: W fp32 -> fp16 ; also zeros g_zmax
// ---------------------------------------------------------------------------
__global__ void k_prep(const float* __restrict__ pw) {
    int i = blockIdx.x * blockDim.x + threadIdx.x;   // COUT*CIN = 131072
    g_wh[i] = __float2half_rn(pw[i]);
    if (i < N_ * COUT) g_zmax[i] = 0;
}

// ---------------------------------------------------------------------------
// K1: depthwise 3x3 + bias + BN1 + ReLU + per-plane cut; writes fp16
// ---------------------------------------------------------------------------
__global__ __launch_bounds__(224)
void k_dw(const float* __restrict__ x,
          const float* __restrict__ dww,  const float* __restrict__ dwb,
          const float* __restrict__ g1,   const float* __restrict__ b1,
          const float* __restrict__ m1,   const float* __restrict__ v1)
{
    __shared__ float sx[58 * 58];
    __shared__ float wmax[8];

    const int bid = blockIdx.x;            // n*CIN + c
    const int c   = bid & (CIN - 1);
    const int tid = threadIdx.x;
    const float* __restrict__ xp = x + (size_t)bid * HW;

    for (int i = tid; i < 58 * 58; i += 224) {
        int r = i / 58, q = i - r * 58;
        int gh = r - 1, gw = q - 1;
        float v = 0.f;
        if ((unsigned)gh < 56u && (unsigned)gw < 56u) v = xp[gh * 56 + gw];
        sx[i] = v;
    }

    const float ww0 = __ldg(&dww[c*9+0]), ww1 = __ldg(&dww[c*9+1]), ww2 = __ldg(&dww[c*9+2]);
    const float ww3 = __ldg(&dww[c*9+3]), ww4 = __ldg(&dww[c*9+4]), ww5 = __ldg(&dww[c*9+5]);
    const float ww6 = __ldg(&dww[c*9+6]), ww7 = __ldg(&dww[c*9+7]), ww8 = __ldg(&dww[c*9+8]);
    const float a  = __ldg(&g1[c]) * rsqrtf(__ldg(&v1[c]) + EPSV);
    const float sh = __ldg(&b1[c]) - __ldg(&m1[c]) * a + __ldg(&dwb[c]) * a;

    __syncthreads();

    float v[14];
    float lmax = 0.f;
    const int h0 = tid / 56;               // 0..3
    const int w0 = tid - h0 * 56;
    const float* p = sx + h0 * 58 + w0;
    #pragma unroll
    for (int j = 0; j < 14; ++j) {
        float acc = p[0]   * ww0 + p[1]   * ww1 + p[2]   * ww2
                  + p[58]  * ww3 + p[59]  * ww4 + p[60]  * ww5
                  + p[116] * ww6 + p[117] * ww7 + p[118] * ww8;
        v[j] = fmaxf(fmaf(acc, a, sh), 0.f);
        lmax = fmaxf(lmax, v[j]);
        p += 4 * 58;
    }
    #pragma unroll
    for (int o = 16; o; o >>= 1) lmax = fmaxf(lmax, __shfl_xor_sync(~0u, lmax, o));
    if ((tid & 31) == 0) wmax[tid >> 5] = lmax;
    __syncthreads();
    if (tid == 0) {
        float m = wmax[0];
        #pragma unroll
        for (int i = 1; i < 7; ++i) m = fmaxf(m, wmax[i]);
        wmax[0] = m;
    }
    __syncthreads();
    const bool cut = wmax[0] < DW_TH;

    __half* __restrict__ yp = g_yh + (size_t)bid * HW;
    #pragma unroll
    for (int j = 0; j < 14; ++j)
        yp[tid + j * 224] = __float2half_rn(cut ? 0.f : v[j]);
}

// ---------------------------------------------------------------------------
// K2: mma.sync fp16 single-pass GEMM: D = Y.W (both fp16, fp32 accum).
// 4-stage cp.async pipeline, KC=32. Fused BN2 + ReLU + per-(n,o) max.
// ---------------------------------------------------------------------------
__global__ __launch_bounds__(256, 2)
void k_pw(const float* __restrict__ pb,
          const float* __restrict__ g2,  const float* __restrict__ b2v,
          const float* __restrict__ m2,  const float* __restrict__ v2,
          float* __restrict__ out)
{
    extern __shared__ char smem[];
    const uint32_t sb = smem_u32(smem);
    const int tid  = threadIdx.x;
    const int wid  = tid >> 5;
    const int lane = tid & 31;
    const int wm   = wid & 1;          // 2 m-warps (hw, 32 each)
    const int wn   = wid >> 1;         // 4 n-warps (o, 32 each)
    const int qg   = lane >> 3;
    const int rr   = lane & 7;
    const int g    = lane >> 2;
    const int t    = lane & 3;

    const int o0  = blockIdx.x * TN_O;     // 4
    const int hw0 = blockIdx.y * TM_HW;    // 49
    const int n   = blockIdx.z;            // 32

    float* a2s  = (float*)(smem + OFF_EPI);
    float* sh2s = (float*)(smem + OFF_EPI + TN_O * 4);
    int*   smax = (int*)  (smem + OFF_EPI + TN_O * 8);
    if (tid < TN_O) {
        const int o = o0 + tid;
        float a2 = __ldg(&g2[o]) * rsqrtf(__ldg(&v2[o]) + EPSV);
        a2s[tid]  = a2;
        sh2s[tid] = __ldg(&b2v[o]) - __ldg(&m2[o]) * a2 + __ldg(&pb[o]) * a2;
        smax[tid] = 0;
    }

    const __half* __restrict__ yn = g_yh + (size_t)n * CIN * HW;

    auto fill = [&](int slot, int ck) {
        const uint32_t s0 = sb + slot * STAGE;
        const int k0 = ck * KC;
        {   // Y: 32 rows x 8 chunks = 256 cp
            int row = tid >> 3, ch = tid & 7;
            cp16(s0 + OFF_Y + row * YROW + ch * 16,
                 yn + (size_t)(k0 + row) * HW + hw0 + ch * 8);
        }
        #pragma unroll
        for (int it = 0; it < 2; ++it) {   // W: 128 rows x 4 chunks = 512 cp
            int idx = tid + it * 256;
            int row = idx >> 2, ch = idx & 3;
            cp16(s0 + OFF_W + row * WROW + ch * 16,
                 g_wh + (size_t)(o0 + row) * CIN + k0 + ch * 8);
        }
    };

    float acc[2][4][4];
    #pragma unroll
    for (int i = 0; i < 2; ++i)
        #pragma unroll
        for (int j = 0; j < 4; ++j)
            #pragma unroll
            for (int r = 0; r < 4; ++r) acc[i][j][r] = 0.f;

    fill(0, 0); CP_COMMIT();
    fill(1, 1); CP_COMMIT();
    fill(2, 2); CP_COMMIT();

    // A (Y, trans): row = s*16 + aRow ; col byte = wm*64 + (qg&1)*16 + i*32
    const uint32_t aRow  = (qg >> 1) * 8 + rr;
    const uint32_t aColB = wm * 64 + (qg & 1) * 16;
    // B (W): row = wn*32 + jp*16 + (qg>>1)*8 + rr ; col byte = s*32 + (qg&1)*16
    const uint32_t bRow  = wn * 32 + (qg >> 1) * 8 + rr;
    const uint32_t bColB = (qg & 1) * 16;

    for (int ck = 0; ck < NKC; ++ck) {
        CP_WAIT2();
        __syncthreads();
        const uint32_t s0 = sb + (ck & 3) * STAGE;
        const uint32_t yB = s0 + OFF_Y;
        const uint32_t wB = s0 + OFF_W;

        #pragma unroll
        for (int s = 0; s < KC / 16; ++s) {
            uint32_t bm[2][4];
            #pragma unroll
            for (int jp = 0; jp < 2; ++jp)
                ldsm4(bm[jp], wB + (bRow + jp * 16) * WROW + bColB + s * 32);
            #pragma unroll
            for (int i = 0; i < 2; ++i) {
                uint32_t av[4];
                ldsm4t(av, yB + (s * 16 + aRow) * YROW + aColB + i * 32);
                #pragma unroll
                for (int jp = 0; jp < 2; ++jp) {
                    #pragma unroll
                    for (int jj = 0; jj < 2; ++jj)
                        mma_f16(acc[i][jp * 2 + jj], av, bm[jp][jj * 2], bm[jp][jj * 2 + 1]);
                }
            }
        }
        if (ck + 3 < NKC) fill((ck + 3) & 3, ck + 3);
        CP_COMMIT();
    }

    // ---- epilogue ----
    float* __restrict__ outn = out + (size_t)n * COUT * HW;
    #pragma unroll
    for (int i = 0; i < 2; ++i) {
        const int hwa = hw0 + wm * 32 + i * 16 + g;
        #pragma unroll
        for (int j = 0; j < 4; ++j) {
            const int col = wn * 32 + j * 8 + t * 2;
            const int o   = o0 + col;
            const float a20 = a2s[col],     sh0 = sh2s[col];
            const float a21 = a2s[col + 1], sh1 = sh2s[col + 1];
            float z0 = fmaxf(fmaf(acc[i][j][0], a20, sh0), 0.f);
            float z1 = fmaxf(fmaf(acc[i][j][1], a21, sh1), 0.f);
            float z2 = fmaxf(fmaf(acc[i][j][2], a20, sh0), 0.f);
            float z3 = fmaxf(fmaf(acc[i][j][3], a21, sh1), 0.f);
            outn[(size_t)o * HW + hwa]           = z0;
            outn[(size_t)(o + 1) * HW + hwa]     = z1;
            outn[(size_t)o * HW + hwa + 8]       = z2;
            outn[(size_t)(o + 1) * HW + hwa + 8] = z3;
            atomicMax(&smax[col],     __float_as_int(fmaxf(z0, z2)));
            atomicMax(&smax[col + 1], __float_as_int(fmaxf(z1, z3)));
        }
    }
    __syncthreads();
    if (tid < TN_O)
        atomicMax(&g_zmax[n * COUT + o0 + tid], smax[tid]);
}

// ---------------------------------------------------------------------------
// K3: zero planes whose max < 1e-3
// ---------------------------------------------------------------------------
__global__ __launch_bounds__(256)
void k_cut(float* __restrict__ out)
{
    const int base = blockIdx.x * 8;
    for (int p = 0; p < 8; ++p) {
        const int plane = base + p;
        if (__int_as_float(g_zmax[plane]) >= PW_TH) continue;
        float* __restrict__ q = out + (size_t)plane * HW;
        for (int i = threadIdx.x; i < HW; i += 256) q[i] = 0.f;
    }
}

// ---------------------------------------------------------------------------
extern "C" void kernel_launch(void* const* d_in, const int* in_sizes, int n_in,
                              void* d_out, int out_size)
{
    const float* x    = (const float*)d_in[0];
    const float* dww  = (const float*)d_in[1];
    const float* dwb  = (const float*)d_in[2];
    const float* g1   = (const float*)d_in[3];
    const float* b1   = (const float*)d_in[4];
    const float* m1   = (const float*)d_in[5];
    const float* v1   = (const float*)d_in[6];
    const float* pw   = (const float*)d_in[7];
    const float* pb   = (const float*)d_in[8];
    const float* g2   = (const float*)d_in[9];
    const float* b2   = (const float*)d_in[10];
    const float* m2   = (const float*)d_in[11];
    const float* v2   = (const float*)d_in[12];
    float* out = (float*)d_out;

    cudaFuncSetAttribute(k_pw, cudaFuncAttributeMaxDynamicSharedMemorySize, SMEM_PW);

    k_prep<<<(COUT * CIN) / 256, 256>>>(pw);
    k_dw<<<N_ * CIN, 224>>>(x, dww, dwb, g1, b1, m1, v1);
    dim3 grid(COUT / TN_O, HW / TM_HW, N_);   // 4 x 49 x 32 (o fastest for Y L2 reuse)
    k_pw<<<grid, 256, SMEM_PW>>>(pb, g2, b2, m2, v2, out);
    k_cut<<<(N_ * COUT) / 8, 256>>>(out);
}